// round 8
// baseline (speedup 1.0000x reference)
#include <cuda_runtime.h>
#include <stdint.h>

// Problem constants
#define PQ 400
#define PP 200000
#define NB 100
#define NCTA 148
#define NTH 544                          // 17 warps
#define NWPC 17
#define NWARP_TOT (NCTA * NWPC)          // 2516 warps chip-wide
#define ROW_F4 (PP / 4)                  // 50,000 float4 per row
#define TOT_F4 ((long long)PQ * ROW_F4)  // 20,000,000

typedef unsigned long long u64;
typedef unsigned int u32;

// Device scratch (no allocations allowed)
__device__ unsigned char d_lab8[PP];
__device__ float d_GN[NB * PQ];   // sum of (sel - 0.25(A+B)) = -(f1-f0) per (label,q)
__device__ float d_Pb[NB * PQ];   // sum of sigmoid per (label,q)
__device__ float d_Sel[PQ];       // sum of sel per q
__device__ int   d_cnt[NB];

// ---------------------------------------------------------------------------
// f32x2 / misc PTX helpers
// ---------------------------------------------------------------------------
#define FMA2(d, a, b, c) asm("fma.rn.f32x2 %0, %1, %2, %3;" : "=l"(d) : "l"(a), "l"(b), "l"(c))
#define MUL2(d, a, b)    asm("mul.rn.f32x2 %0, %1, %2;"     : "=l"(d) : "l"(a), "l"(b))
#define ADD2(d, a, b)    asm("add.rn.f32x2 %0, %1, %2;"     : "=l"(d) : "l"(a), "l"(b))
#define HADD2(d, a)      asm("add.rn.bf16x2 %0, %0, %1;"    : "+r"(d) : "r"(a))

__device__ __forceinline__ u64 pk2(float lo, float hi) {
    u64 r; asm("mov.b64 %0, {%1, %2};" : "=l"(r) : "f"(lo), "f"(hi)); return r;
}
__device__ __forceinline__ u64 bcast2(float v) {
    u64 r; asm("mov.b64 %0, {%1, %1};" : "=l"(r) : "f"(v)); return r;
}
__device__ __forceinline__ void upk2(u64 v, float& lo, float& hi) {
    asm("mov.b64 {%0, %1}, %2;" : "=f"(lo), "=f"(hi) : "l"(v));
}
__device__ __forceinline__ float ex2f(float x) {
    float r; asm("ex2.approx.ftz.f32 %0, %1;" : "=f"(r) : "f"(x)); return r;
}
__device__ __forceinline__ float rcpf(float x) {
    float r; asm("rcp.approx.ftz.f32 %0, %1;" : "=f"(r) : "f"(x)); return r;
}
__device__ __forceinline__ float slctf(float a, float b, float c) { // c>=0 ? a : b
    float d; asm("slct.f32.f32 %0, %1, %2, %3;" : "=f"(d) : "f"(a), "f"(b), "f"(c)); return d;
}
__device__ __forceinline__ u32 smem_u32(const void* p) {
    u32 a; asm("{ .reg .u64 t; cvta.to.shared.u64 t, %1; cvt.u32.u64 %0, t; }" : "=r"(a) : "l"(p));
    return a;
}
// pack {lo=g, hi=p} as bf16x2
__device__ __forceinline__ u32 cvt_gp(float g, float p) {
    u32 r; asm("cvt.rn.bf16x2.f32 %0, %1, %2;" : "=r"(r) : "f"(p), "f"(g)); return r;
}

// Private-column bin RMW: LDS.32 + packed bf16 add + STS.32 (no atomics, no races)
__device__ __forceinline__ void bin_rmw(u32 addr, u32 add) {
    u32 v;
    asm volatile("ld.shared.b32 %0, [%1];" : "=r"(v) : "r"(addr));
    asm("add.rn.bf16x2 %0, %0, %1;" : "+r"(v) : "r"(add));
    asm volatile("st.shared.b32 [%0], %1;" :: "r"(addr), "r"(v) : "memory");
}

// Loop-invariant packed constants (8 u64 = 16 regs)
struct PkConsts {
    u64 nl2e, one;
    u64 e4, e3, e2, e1, e0;   // ln(1+e) deg-4 minimax rebased in e on [0,1]
    u64 negq;
};
__device__ __forceinline__ PkConsts make_consts() {
    PkConsts K;
    K.nl2e = bcast2(-1.4426950408889634f);
    K.one  = bcast2(1.0f);
    K.e4 = bcast2(-5.4869696e-2f);
    K.e3 = bcast2( 2.16735288e-1f);
    K.e2 = bcast2(-4.64506268e-1f);
    K.e1 = bcast2( 9.9554191e-1f);
    K.e0 = bcast2( 6.9151e-5f);
    K.negq = bcast2(-0.25f);
    return K;
}

// ---------------------------------------------------------------------------
// pair2: 2 elements -> two bf16x2 {g,p} bin contributions; selacc += sel (f32x2)
// ---------------------------------------------------------------------------
__device__ __forceinline__ void pair2(u64 X, const PkConsts& K,
                                      u32& bin0, u32& bin1, u64& selacc) {
    u64 AX = X & 0x7FFFFFFF7FFFFFFFull;
    u64 T;  MUL2(T, AX, K.nl2e);
    float t0, t1; upk2(T, t0, t1);
    u64 E = pk2(ex2f(t0), ex2f(t1));
    u64 EP1; ADD2(EP1, E, K.one);
    float q0, q1; upk2(EP1, q0, q1);
    u64 S = pk2(rcpf(q0), rcpf(q1));   // s = 1/(1+e) = sigmoid(|x|)

    u64 L;                             // L = log1p(e), Horner in e (4 FMA2)
    FMA2(L, E, K.e4, K.e3);
    FMA2(L, L, E, K.e2);
    FMA2(L, L, E, K.e1);
    FMA2(L, L, E, K.e0);

    u64 OS;  MUL2(OS, E, S);           // sigmoid(-|x|)
    u64 AXL; ADD2(AXL, AX, L);
    u64 OS2; MUL2(OS2, OS, OS);
    u64 Apk; MUL2(Apk, OS2, L);        // A = os^2 * L
    u64 S2;  MUL2(S2, S, S);
    u64 Bpk; MUL2(Bpk, S2, AXL);       // B = s^2 * (|x|+L)
    u64 ABpk; ADD2(ABpk, Apk, Bpk);

    float a0, a1, b0, b1, x0, x1, os0, os1, s0, s1;
    upk2(Apk, a0, a1); upk2(Bpk, b0, b1);
    upk2(X, x0, x1); upk2(OS, os0, os1); upk2(S, s0, s1);

    float sel0 = slctf(b0, a0, x0);   // x>=0 ? B : A
    float sel1 = slctf(b1, a1, x1);
    float p0   = slctf(s0, os0, x0);  // x>=0 ? s : os
    float p1   = slctf(s1, os1, x1);

    u64 SEL = pk2(sel0, sel1);
    u64 GN;  FMA2(GN, ABpk, K.negq, SEL);   // gneg = sel - 0.25(A+B) = -(f1-f0)
    ADD2(selacc, selacc, SEL);

    float gn0, gn1; upk2(GN, gn0, gn1);
    bin0 = cvt_gp(gn0, p0);
    bin1 = cvt_gp(gn1, p1);
}

__device__ __forceinline__ void proc_f4(float4 x, u32 lb, u32 sb,
                                        const PkConsts& K, u64& selpk) {
    u32 b0, b1, b2, b3;
    pair2(pk2(x.x, x.y), K, b0, b1, selpk);
    pair2(pk2(x.z, x.w), K, b2, b3, selpk);
    bin_rmw(sb + ( lb        & 0xFFu) * (NTH * 4u), b0);
    bin_rmw(sb + ((lb >>  8) & 0xFFu) * (NTH * 4u), b1);
    bin_rmw(sb + ((lb >> 16) & 0xFFu) * (NTH * 4u), b2);
    bin_rmw(sb + ( lb >> 24         ) * (NTH * 4u), b3);
}

// ---------------------------------------------------------------------------
// Main kernel: flat warp ranges, thread-private bf16x2 bin columns,
// depth-2 x 2-float4 software pipeline (low register pressure)
// ---------------------------------------------------------------------------
__global__ __launch_bounds__(NTH, 1) void cost_kernel(const float* __restrict__ pm) {
    extern __shared__ u32 bins[];   // [NB][NTH] bf16x2 {g,p}, column = tid (private)
    int tid = threadIdx.x, wid = tid >> 5, lane = tid & 31;

    #pragma unroll 4
    for (int j = 0; j < NB; j++) bins[j * NTH + tid] = 0u;
    // no __syncthreads needed: columns are strictly thread-private

    const PkConsts K = make_consts();
    u32 sb = smem_u32(bins) + (u32)tid * 4u;

    u64 gw = (u64)blockIdx.x * NWPC + (u64)wid;
    long long beg = (long long)(gw * (u64)TOT_F4 / NWARP_TOT);
    long long end = (long long)((gw + 1) * (u64)TOT_F4 / NWARP_TOT);

    const u32* lv = reinterpret_cast<const u32*>(d_lab8);  // uchar4 per float4

    while (beg < end) {
        int row = (int)(beg / ROW_F4);
        long long rend = (long long)(row + 1) * ROW_F4;
        if (rend > end) rend = end;
        int c0 = (int)(beg - (long long)row * ROW_F4);
        int cn = (int)(rend - (long long)row * ROW_F4);

        const float4* xr = reinterpret_cast<const float4*>(pm + (size_t)row * PP);

        u64 selpk = 0ull;
        int cL = c0 + lane;
        int nfull = (cn - c0) >> 6;      // full 64-f4 batches (2 f4/lane)

        float4 xa, xb; u32 la, lb;
        float4 ya, yb; u32 ma, mb;

        if (nfull > 0) {
            xa = __ldcs(xr + cL);       la = lv[cL];
            xb = __ldcs(xr + cL + 32);  lb = lv[cL + 32];
            for (int i = 1; i < nfull; i++) {
                int cc = cL + (i << 6);
                ya = __ldcs(xr + cc);       ma = lv[cc];
                yb = __ldcs(xr + cc + 32);  mb = lv[cc + 32];
                proc_f4(xa, la, sb, K, selpk);
                proc_f4(xb, lb, sb, K, selpk);
                xa = ya; la = ma; xb = yb; lb = mb;
            }
            proc_f4(xa, la, sb, K, selpk);
            proc_f4(xb, lb, sb, K, selpk);
            cL += nfull << 6;
        }
        for (; cL < cn; cL += 32)
            proc_f4(__ldcs(xr + cL), lv[cL], sb, K, selpk);

        // ---- segment flush (row uniform across warp) ----
        {
            float slo, shi; upk2(selpk, slo, shi);
            float sv = slo + shi;
            #pragma unroll
            for (int o = 16; o; o >>= 1)
                sv += __shfl_xor_sync(0xFFFFFFFFu, sv, o);
            if (lane == 0) atomicAdd(&d_Sel[row], sv);

            for (int j = 0; j < NB; j++) {
                u32 v = bins[j * NTH + tid];
                bins[j * NTH + tid] = 0u;
                // 3 packed bf16 reduce levels (16, 8, 4)
                u32 t;
                t = __shfl_xor_sync(0xFFFFFFFFu, v, 16); HADD2(v, t);
                t = __shfl_xor_sync(0xFFFFFFFFu, v, 8);  HADD2(v, t);
                t = __shfl_xor_sync(0xFFFFFFFFu, v, 4);  HADD2(v, t);
                // unpack, finish in f32 (levels 2, 1)
                float g = __uint_as_float(v << 16);
                float p = __uint_as_float(v & 0xFFFF0000u);
                #pragma unroll
                for (int o = 2; o; o >>= 1) {
                    g += __shfl_xor_sync(0xFFFFFFFFu, g, o);
                    p += __shfl_xor_sync(0xFFFFFFFFu, p, o);
                }
                if (lane == 0)  atomicAdd(&d_GN[j * PQ + row], g);
                if (lane == 16) atomicAdd(&d_Pb[j * PQ + row], p);
            }
        }
        beg = rend;
    }
}

// ---------------------------------------------------------------------------
// Zero d_cnt (must precede prep's atomics)
// ---------------------------------------------------------------------------
__global__ void zero_kernel() {
    if (threadIdx.x < NB) d_cnt[threadIdx.x] = 0;
}

// ---------------------------------------------------------------------------
// Prep: labels int32 -> uint8, histogram counts, zero accumulators
// ---------------------------------------------------------------------------
__global__ void prep_kernel(const int* __restrict__ labels) {
    __shared__ int h[NB];
    if (threadIdx.x < NB) h[threadIdx.x] = 0;
    __syncthreads();

    int i = blockIdx.x * blockDim.x + threadIdx.x;
    if (i < NB * PQ) { d_GN[i] = 0.f; d_Pb[i] = 0.f; }
    if (i < PQ) d_Sel[i] = 0.f;

    if (i < PP / 4) {
        int4 l4 = reinterpret_cast<const int4*>(labels)[i];
        uchar4 u;
        u.x = (unsigned char)l4.x; u.y = (unsigned char)l4.y;
        u.z = (unsigned char)l4.z; u.w = (unsigned char)l4.w;
        reinterpret_cast<uchar4*>(d_lab8)[i] = u;
        atomicAdd(&h[l4.x], 1);
        atomicAdd(&h[l4.y], 1);
        atomicAdd(&h[l4.z], 1);
        atomicAdd(&h[l4.w], 1);
    }
    __syncthreads();
    if (threadIdx.x < NB && h[threadIdx.x] != 0)
        atomicAdd(&d_cnt[threadIdx.x], h[threadIdx.x]);
}

// ---------------------------------------------------------------------------
// Finalize: out[q,j] = cost_mask + cost_dice
// ---------------------------------------------------------------------------
__global__ void finalize_kernel(float* __restrict__ out) {
    int q = blockIdx.x, j = threadIdx.x;   // 128 threads
    __shared__ float red[4];

    float pv = (j < NB) ? d_Pb[j * PQ + q] : 0.f;
    float w = pv;
    #pragma unroll
    for (int o = 16; o; o >>= 1)
        w += __shfl_xor_sync(0xFFFFFFFFu, w, o);
    if ((j & 31) == 0) red[j >> 5] = w;
    __syncthreads();
    float Psum = red[0] + red[1] + red[2] + red[3];

    if (j < NB) {
        float G   = -d_GN[j * PQ + q];
        float cm  = (G + 0.75f * d_Sel[q]) * (1.0f / (float)PP);
        float num = fmaf(2.0f, pv, 1.0f);
        float den = Psum + (float)d_cnt[j] + 1.0f;
        out[q * NB + j] = cm + 1.0f - num / den;
    }
}

// ---------------------------------------------------------------------------
extern "C" void kernel_launch(void* const* d_in, const int* in_sizes, int n_in,
                              void* d_out, int out_size) {
    const float* pm     = (const float*)d_in[0];
    const int*   labels = (const int*)d_in[1];
    (void)in_sizes; (void)n_in; (void)out_size;

    const int smem = NB * NTH * 4;  // 217,600 B (17 warps per SM)
    cudaFuncSetAttribute(cost_kernel, cudaFuncAttributeMaxDynamicSharedMemorySize, smem);

    zero_kernel<<<1, 128>>>();
    prep_kernel<<<(PP / 4 + 255) / 256, 256>>>(labels);
    cost_kernel<<<NCTA, NTH, smem>>>(pm);
    finalize_kernel<<<PQ, 128>>>((float*)d_out);
}